// round 2
// baseline (speedup 1.0000x reference)
#include <cuda_runtime.h>
#include <cstdint>

#define MAXN 100000
#define MAXE 1600000
#define DIN  64

// ---------------- scratch (no cudaMalloc allowed) ----------------
__device__ float g_PQ[(size_t)MAXN * 128];    // P|Q per node (reused as [N,8] for layer 3)
__device__ float g_HA[(size_t)MAXN * 64];
__device__ float g_HB[(size_t)MAXN * 64];
__device__ int   g_counts[MAXN];
__device__ int   g_off[MAXN + 1];
__device__ int   g_cursor[MAXN];
__device__ int2  g_meta[MAXE];                // {src, __float_as_int(e)} sorted by dst

// =================================================================
// CSR build: histogram -> single-block scan -> scatter
// =================================================================
__global__ void hist_kernel(const int* __restrict__ ei, int* __restrict__ counts, int E)
{
    int e = blockIdx.x * blockDim.x + threadIdx.x;
    if (e < E) atomicAdd(&counts[__ldg(ei + E + e)], 1);
}

__global__ __launch_bounds__(1024) void scan_kernel(const int* __restrict__ counts,
                                                    int* __restrict__ off,
                                                    int* __restrict__ cursor, int N)
{
    __shared__ int ssum[1024];
    int tid = threadIdx.x;
    int chunk = (N + 1023) / 1024;
    int lo = tid * chunk;
    int hi = min(lo + chunk, N);
    int s = 0;
    for (int i = lo; i < hi; i++) s += counts[i];
    ssum[tid] = s;
    __syncthreads();
    // inclusive Hillis-Steele scan
    for (int d = 1; d < 1024; d <<= 1) {
        int v = (tid >= d) ? ssum[tid - d] : 0;
        __syncthreads();
        ssum[tid] += v;
        __syncthreads();
    }
    int base = (tid == 0) ? 0 : ssum[tid - 1];
    for (int i = lo; i < hi; i++) {
        off[i] = base; cursor[i] = base;
        base += counts[i];
    }
    if (tid == 0) off[N] = ssum[1023];
}

__global__ void scatter_kernel(const int* __restrict__ ei, const float* __restrict__ ea,
                               int* __restrict__ cursor, int2* __restrict__ meta, int E)
{
    int e = blockIdx.x * blockDim.x + threadIdx.x;
    if (e >= E) return;
    int s = __ldg(ei + e);
    int d = __ldg(ei + E + e);
    int pos = atomicAdd(&cursor[d], 1);
    meta[pos] = make_int2(s, __float_as_int(__ldg(ea + e)));
}

// =================================================================
// Fused GEMM: PQ[row,0:64]=X@Wm, PQ[row,64:128]=X@Bm, H[row,:]=X@Wr+b
// 256 threads, 32-row tile, transposed X in shared for LDS.128 reads.
// Dynamic smem: sXT(64*36) | sWm(4096) | sBm(4096) | sWr(4096) | sb(64)
// =================================================================
#define GEMM_SMEM_FLOATS (64*36 + 4096*3 + 64)
#define GEMM_SMEM_BYTES  (GEMM_SMEM_FLOATS * 4)

template<bool RELU>
__global__ __launch_bounds__(256) void gemm_fused(const float* __restrict__ X,
                                                  const float* __restrict__ Wm,
                                                  const float* __restrict__ Bm,
                                                  const float* __restrict__ Wr,
                                                  const float* __restrict__ bias,
                                                  float* __restrict__ PQ,
                                                  float* __restrict__ H, int N)
{
    extern __shared__ float sm[];
    float* sXT = sm;                 // [k*36 + row], 64 k x 32 rows (pad 36)
    float* sWm = sm + 64 * 36;
    float* sBm = sWm + 4096;
    float* sWr = sBm + 4096;
    float* sb  = sWr + 4096;

    const int tid = threadIdx.x;
    const int tx = tid & 63;
    const int ty = tid >> 6;         // 0..3
    const int row0 = blockIdx.x * 32;

    #pragma unroll
    for (int i = tid; i < 4096; i += 256) { sWm[i] = Wm[i]; sBm[i] = Bm[i]; sWr[i] = Wr[i]; }
    if (tid < 64) sb[tid] = bias[tid];

    // stage X tile transposed: global coalesced read, shared transposed store
    #pragma unroll
    for (int i = tid; i < 2048; i += 256) {
        int r = i >> 6;              // row in tile
        int k = i & 63;
        int row = row0 + r;
        float v = (row < N) ? X[(size_t)row * 64 + k] : 0.f;
        if (RELU) v = fmaxf(v, 0.f);
        sXT[k * 36 + r] = v;
    }
    __syncthreads();

    float accp[8], accq[8], accr[8];
    #pragma unroll
    for (int r = 0; r < 8; r++) { accp[r] = 0.f; accq[r] = 0.f; accr[r] = 0.f; }

    #pragma unroll 8
    for (int k = 0; k < 64; k++) {
        float4 xa = *reinterpret_cast<const float4*>(&sXT[k * 36 + ty * 8]);
        float4 xb = *reinterpret_cast<const float4*>(&sXT[k * 36 + ty * 8 + 4]);
        float wm = sWm[k * 64 + tx];
        float wb = sBm[k * 64 + tx];
        float wr = sWr[k * 64 + tx];
        float xs[8] = {xa.x, xa.y, xa.z, xa.w, xb.x, xb.y, xb.z, xb.w};
        #pragma unroll
        for (int r = 0; r < 8; r++) {
            accp[r] = fmaf(xs[r], wm, accp[r]);
            accq[r] = fmaf(xs[r], wb, accq[r]);
            accr[r] = fmaf(xs[r], wr, accr[r]);
        }
    }

    float b = sb[tx];
    #pragma unroll
    for (int r = 0; r < 8; r++) {
        int row = row0 + ty * 8 + r;
        if (row < N) {
            PQ[(size_t)row * 128 + tx]      = accp[r];
            PQ[(size_t)row * 128 + 64 + tx] = accq[r];
            H[(size_t)row * 64 + tx]        = accr[r] + b;
        }
    }
}

// =================================================================
// dst-centric aggregation, d=64: one warp per node, no atomics.
// H[i] += sum_{edges->i} e * P[src] + Q[src]
// =================================================================
__global__ __launch_bounds__(256) void agg64_kernel(const int* __restrict__ off,
                                                    const int2* __restrict__ meta,
                                                    const float* __restrict__ PQ,
                                                    float* __restrict__ H, int N)
{
    int w = (blockIdx.x * blockDim.x + threadIdx.x) >> 5;
    int lane = threadIdx.x & 31;
    if (w >= N) return;

    int beg = __ldg(off + w);
    int end = __ldg(off + w + 1);

    float2 acc = make_float2(0.f, 0.f);
    for (int k = beg; k < end; k++) {
        int2 me = __ldg(meta + k);
        int s = me.x;
        float e = __int_as_float(me.y);
        const float* base = PQ + (size_t)s * 128 + lane * 2;
        float2 p = *reinterpret_cast<const float2*>(base);
        float2 q = *reinterpret_cast<const float2*>(base + 64);
        acc.x = fmaf(e, p.x, acc.x) + q.x;
        acc.y = fmaf(e, p.y, acc.y) + q.y;
    }

    float* hp = H + (size_t)w * 64 + lane * 2;
    float2 h = *reinterpret_cast<float2*>(hp);
    h.x += acc.x; h.y += acc.y;
    *reinterpret_cast<float2*>(hp) = h;
}

// =================================================================
// Layer 3: PQ3[row,0:4]=relu(X)@Wm, [4:8]=relu(X)@Bm, OUT=relu(X)@Wr+b
// =================================================================
__global__ __launch_bounds__(256) void gemm3_kernel(const float* __restrict__ X,
                                                    const float* __restrict__ Wm,
                                                    const float* __restrict__ Bm,
                                                    const float* __restrict__ Wr,
                                                    const float* __restrict__ b,
                                                    float* __restrict__ PQ3,
                                                    float* __restrict__ OUT, int N)
{
    __shared__ float sw[768];
    int tid = threadIdx.x;
    if (tid < 256) { sw[tid] = Wm[tid]; sw[256 + tid] = Bm[tid]; sw[512 + tid] = Wr[tid]; }
    __syncthreads();

    int row = blockIdx.x * blockDim.x + tid;
    if (row >= N) return;

    float accp[4] = {0,0,0,0}, accq[4] = {0,0,0,0}, accr[4] = {0,0,0,0};
    const float4* xr = reinterpret_cast<const float4*>(X + (size_t)row * 64);
    #pragma unroll
    for (int k4 = 0; k4 < 16; k4++) {
        float4 xv4 = __ldg(xr + k4);
        float xs[4] = {xv4.x, xv4.y, xv4.z, xv4.w};
        #pragma unroll
        for (int j = 0; j < 4; j++) {
            float xv = fmaxf(xs[j], 0.f);
            int k = k4 * 4 + j;
            #pragma unroll
            for (int c = 0; c < 4; c++) {
                accp[c] = fmaf(xv, sw[k * 4 + c], accp[c]);
                accq[c] = fmaf(xv, sw[256 + k * 4 + c], accq[c]);
                accr[c] = fmaf(xv, sw[512 + k * 4 + c], accr[c]);
            }
        }
    }
    #pragma unroll
    for (int c = 0; c < 4; c++) {
        PQ3[(size_t)row * 8 + c]     = accp[c];
        PQ3[(size_t)row * 8 + 4 + c] = accq[c];
        OUT[(size_t)row * 4 + c]     = accr[c] + b[c];
    }
}

// dst-centric edge for d_out=4: one thread per node (tiny volume)
__global__ __launch_bounds__(256) void agg4_kernel(const int* __restrict__ off,
                                                   const int2* __restrict__ meta,
                                                   const float* __restrict__ PQ3,
                                                   float* __restrict__ OUT, int N)
{
    int w = blockIdx.x * blockDim.x + threadIdx.x;
    if (w >= N) return;
    int beg = __ldg(off + w);
    int end = __ldg(off + w + 1);
    float4 acc = make_float4(0.f, 0.f, 0.f, 0.f);
    for (int k = beg; k < end; k++) {
        int2 me = __ldg(meta + k);
        int s = me.x;
        float e = __int_as_float(me.y);
        const float4* pq = reinterpret_cast<const float4*>(PQ3) + (size_t)s * 2;
        float4 p = __ldg(pq);
        float4 q = __ldg(pq + 1);
        acc.x += fmaf(e, p.x, q.x);
        acc.y += fmaf(e, p.y, q.y);
        acc.z += fmaf(e, p.z, q.z);
        acc.w += fmaf(e, p.w, q.w);
    }
    float4* op = reinterpret_cast<float4*>(OUT + (size_t)w * 4);
    float4 o = *op;
    o.x += acc.x; o.y += acc.y; o.z += acc.z; o.w += acc.w;
    *op = o;
}

__global__ __launch_bounds__(256) void logsoftmax4_kernel(float* __restrict__ OUT, int N)
{
    int row = blockIdx.x * blockDim.x + threadIdx.x;
    if (row >= N) return;
    float4 v = *reinterpret_cast<float4*>(OUT + (size_t)row * 4);
    float m = fmaxf(fmaxf(v.x, v.y), fmaxf(v.z, v.w));
    float s = __expf(v.x - m) + __expf(v.y - m) + __expf(v.z - m) + __expf(v.w - m);
    float lse = m + __logf(s);
    v.x -= lse; v.y -= lse; v.z -= lse; v.w -= lse;
    *reinterpret_cast<float4*>(OUT + (size_t)row * 4) = v;
}

// =================================================================
extern "C" void kernel_launch(void* const* d_in, const int* in_sizes, int n_in,
                              void* d_out, int out_size)
{
    const float* x   = (const float*)d_in[0];
    const int*   ei  = (const int*)  d_in[1];
    const float* ea  = (const float*)d_in[2];
    const float* We1 = (const float*)d_in[3];
    const float* be1 = (const float*)d_in[4];
    const float* Wr1 = (const float*)d_in[5];
    const float* b1  = (const float*)d_in[6];
    const float* We2 = (const float*)d_in[7];
    const float* be2 = (const float*)d_in[8];
    const float* Wr2 = (const float*)d_in[9];
    const float* b2  = (const float*)d_in[10];
    const float* We3 = (const float*)d_in[11];
    const float* be3 = (const float*)d_in[12];
    const float* Wr3 = (const float*)d_in[13];
    const float* b3  = (const float*)d_in[14];

    const int N = in_sizes[0] / DIN;
    const int E = in_sizes[2];

    float *PQ, *HA, *HB;
    int *counts, *off, *cursor;
    int2 *meta;
    cudaGetSymbolAddress((void**)&PQ, g_PQ);
    cudaGetSymbolAddress((void**)&HA, g_HA);
    cudaGetSymbolAddress((void**)&HB, g_HB);
    cudaGetSymbolAddress((void**)&counts, g_counts);
    cudaGetSymbolAddress((void**)&off, g_off);
    cudaGetSymbolAddress((void**)&cursor, g_cursor);
    cudaGetSymbolAddress((void**)&meta, g_meta);
    float* OUT = (float*)d_out;

    cudaFuncSetAttribute(gemm_fused<false>, cudaFuncAttributeMaxDynamicSharedMemorySize, GEMM_SMEM_BYTES);
    cudaFuncSetAttribute(gemm_fused<true>,  cudaFuncAttributeMaxDynamicSharedMemorySize, GEMM_SMEM_BYTES);

    const int gemmGrid  = (N + 31) / 32;
    const int edgeGrid  = (E + 255) / 256;
    const int rowGrid   = (N + 255) / 256;
    const int aggGrid   = (N * 32 + 255) / 256;

    // ---- CSR build (reused by all 3 layers) ----
    cudaMemsetAsync(counts, 0, (size_t)N * sizeof(int));
    hist_kernel<<<edgeGrid, 256>>>(ei, counts, E);
    scan_kernel<<<1, 1024>>>(counts, off, cursor, N);
    scatter_kernel<<<edgeGrid, 256>>>(ei, ea, cursor, meta, E);

    // ---- layer 1 ----
    gemm_fused<false><<<gemmGrid, 256, GEMM_SMEM_BYTES>>>(x, We1, be1, Wr1, b1, PQ, HA, N);
    agg64_kernel<<<aggGrid, 256>>>(off, meta, PQ, HA, N);

    // ---- layer 2 ----
    gemm_fused<true><<<gemmGrid, 256, GEMM_SMEM_BYTES>>>(HA, We2, be2, Wr2, b2, PQ, HB, N);
    agg64_kernel<<<aggGrid, 256>>>(off, meta, PQ, HB, N);

    // ---- layer 3 ----
    gemm3_kernel<<<rowGrid, 256>>>(HB, We3, be3, Wr3, b3, PQ, OUT, N);
    agg4_kernel<<<rowGrid, 256>>>(off, meta, PQ, OUT, N);
    logsoftmax4_kernel<<<rowGrid, 256>>>(OUT, N);
}